// round 4
// baseline (speedup 1.0000x reference)
#include <cuda_runtime.h>
#include <math_constants.h>

#define HW 9216            // 96*96
#define CK 392             // 256 + 136
#define NF (256 * HW)      // visual-feature element count
#define NTOT (CK * HW)     // concat element count = 3612672
#define NCHUNK 32
#define ROWS_PER_CHUNK (HW / NCHUNK)   // 288

// ---- static device scratch (no dynamic allocation allowed) ----
__device__ __align__(16) float g_SRC[NTOT];                 // (9216, 392) row-major
__device__ __align__(16) float g_REF[NTOT];                 // (392, 9216) row-major
__device__ __align__(16) float g_A[(size_t)HW * HW];        // 340 MB logits
__device__ float g_pm[NCHUNK * HW];
__device__ float g_ps[NCHUNK * HW];
__device__ float g_beta[HW], g_gama[HW], g_M[HW];
__device__ float g_colmax[HW], g_wb[HW], g_wg[HW];
__device__ float g_bhat[HW], g_ghat[HW];

// 1) Build the flattened concat buffers. The torch/jax "raw reshape" of the
//    channel-concat is exactly the contiguous flat buffer, so SRC/REF become
//    plain row-major GEMM operands.
__global__ void prep_concat(const float* __restrict__ fs, const float* __restrict__ fr,
                            const float* __restrict__ ls, const float* __restrict__ lr) {
    int t = blockIdx.x * blockDim.x + threadIdx.x;
    if (t >= NTOT) return;
    if (t < NF) {
        g_SRC[t] = 0.01f * fs[t];
        g_REF[t] = 0.01f * fr[t];
    } else {
        g_SRC[t] = ls[t - NF];
        g_REF[t] = lr[t - NF];
    }
}

// 2) 1x1 convs (256->1) + mask equality vector.
__global__ void prep_betagama(const float* __restrict__ fr,
                              const int* __restrict__ ms, const int* __restrict__ mr,
                              const float* __restrict__ w1, const float* __restrict__ b1,
                              const float* __restrict__ w2, const float* __restrict__ b2) {
    int p = blockIdx.x * blockDim.x + threadIdx.x;
    if (p >= HW) return;
    float b = b1[0], g = b2[0];
#pragma unroll 8
    for (int c = 0; c < 256; c++) {
        float v = fr[c * HW + p];          // coalesced across p
        b = fmaf(v, w1[c], b);
        g = fmaf(v, w2[c], g);
    }
    g_beta[p] = b;
    g_gama[p] = g;
    g_M[p] = (ms[p] == mr[p]) ? 1.0f : 0.0f;
}

// 3) fp32 SGEMM: g_A = g_SRC (9216x392) @ g_REF (392x9216).
//    128x128 block tile, BK=8, 256 threads, 8x8 per thread (split 4+4 to keep
//    LDS.128 conflict-free). K=392 = 49*8, M=N divisible by 128: no bounds checks.
__global__ void __launch_bounds__(256) sgemm_kernel() {
    __shared__ __align__(16) float As[8][128];
    __shared__ __align__(16) float Bs[8][128];
    const int tid = threadIdx.x;
    const int tx = tid & 15;        // 0..15  -> N direction
    const int ty = tid >> 4;        // 0..15  -> M direction
    const float* Ab = g_SRC + (size_t)blockIdx.y * 128 * CK;
    const float* Bb = g_REF + (size_t)blockIdx.x * 128;

    const int arow = tid >> 1, acol = (tid & 1) * 4;   // A: 128 rows x 8 k, float4/thread
    const int brow = tid >> 5, bcol = (tid & 31) * 4;  // B: 8 k x 128 cols, float4/thread

    float acc[8][8];
#pragma unroll
    for (int i = 0; i < 8; i++)
#pragma unroll
        for (int j = 0; j < 8; j++) acc[i][j] = 0.0f;

    for (int k0 = 0; k0 < CK; k0 += 8) {
        float4 av = *(const float4*)(Ab + (size_t)arow * CK + k0 + acol);
        float4 bv = *(const float4*)(Bb + (size_t)(k0 + brow) * HW + bcol);
        __syncthreads();
        As[acol + 0][arow] = av.x;
        As[acol + 1][arow] = av.y;
        As[acol + 2][arow] = av.z;
        As[acol + 3][arow] = av.w;
        *(float4*)&Bs[brow][bcol] = bv;
        __syncthreads();
#pragma unroll
        for (int k = 0; k < 8; k++) {
            float4 a0 = *(const float4*)&As[k][ty * 4];
            float4 a1 = *(const float4*)&As[k][ty * 4 + 64];
            float4 b0 = *(const float4*)&Bs[k][tx * 4];
            float4 b1 = *(const float4*)&Bs[k][tx * 4 + 64];
            float ar[8] = {a0.x, a0.y, a0.z, a0.w, a1.x, a1.y, a1.z, a1.w};
            float br[8] = {b0.x, b0.y, b0.z, b0.w, b1.x, b1.y, b1.z, b1.w};
#pragma unroll
            for (int i = 0; i < 8; i++)
#pragma unroll
                for (int j = 0; j < 8; j++) acc[i][j] = fmaf(ar[i], br[j], acc[i][j]);
        }
    }

    const size_t crow0 = (size_t)blockIdx.y * 128 + ty * 4;
    const size_t ccol0 = (size_t)blockIdx.x * 128 + tx * 4;
#pragma unroll
    for (int i = 0; i < 8; i++) {
        size_t r = crow0 + (i & 3) + (i >> 2) * 64;
        float* Cp = g_A + r * HW + ccol0;
        *(float4*)Cp        = make_float4(acc[i][0], acc[i][1], acc[i][2], acc[i][3]);
        *(float4*)(Cp + 64) = make_float4(acc[i][4], acc[i][5], acc[i][6], acc[i][7]);
    }
}

// 4) Per-column online (max, sum-exp) over a 288-row chunk. Thread = one column,
//    consecutive threads = consecutive columns -> fully coalesced A reads.
__global__ void colstats_kernel() {
    int j = blockIdx.x * blockDim.x + threadIdx.x;
    int i0 = blockIdx.y * ROWS_PER_CHUNK;
    float m = -CUDART_INF_F, s = 0.0f;
    const float* col = g_A + (size_t)i0 * HW + j;
    for (int i = 0; i < ROWS_PER_CHUNK; i++) {
        float v = col[(size_t)i * HW];
        float nm = fmaxf(m, v);
        s = s * __expf(m - nm) + __expf(v - nm);
        m = nm;
    }
    g_pm[blockIdx.y * HW + j] = m;
    g_ps[blockIdx.y * HW + j] = s;
}

// 5) Merge chunk partials; fold mask/beta/gama/colsum into per-column weights:
//    wb[j] = M[j]*beta[j]/colsum[j]  (softmax normalizer is over UNMASKED rows,
//    matching reference order softmax -> *M).
__global__ void mergestats_kernel() {
    int j = blockIdx.x * blockDim.x + threadIdx.x;
    float m = -CUDART_INF_F;
    for (int c = 0; c < NCHUNK; c++) m = fmaxf(m, g_pm[c * HW + j]);
    float s = 0.0f;
    for (int c = 0; c < NCHUNK; c++) s += g_ps[c * HW + j] * __expf(g_pm[c * HW + j] - m);
    g_colmax[j] = m;
    float inv = g_M[j] / s;
    g_wb[j] = g_beta[j] * inv;
    g_wg[j] = g_gama[j] * inv;
}

// 6) One warp per row: beta_hat[i] = sum_j exp(A[i,j]-colmax[j]) * wb[j], same for gama.
__global__ void rowsum_kernel() {
    int warp = (blockIdx.x * blockDim.x + threadIdx.x) >> 5;
    int lane = threadIdx.x & 31;
    const float* row = g_A + (size_t)warp * HW;
    float b = 0.0f, g = 0.0f;
    for (int j0 = lane * 4; j0 < HW; j0 += 128) {
        float4 v  = *(const float4*)(row + j0);
        float4 cm = *(const float4*)(g_colmax + j0);
        float4 wb = *(const float4*)(g_wb + j0);
        float4 wg = *(const float4*)(g_wg + j0);
        float e;
        e = __expf(v.x - cm.x); b = fmaf(e, wb.x, b); g = fmaf(e, wg.x, g);
        e = __expf(v.y - cm.y); b = fmaf(e, wb.y, b); g = fmaf(e, wg.y, g);
        e = __expf(v.z - cm.z); b = fmaf(e, wb.z, b); g = fmaf(e, wg.z, g);
        e = __expf(v.w - cm.w); b = fmaf(e, wb.w, b); g = fmaf(e, wg.w, g);
    }
#pragma unroll
    for (int o = 16; o > 0; o >>= 1) {
        b += __shfl_down_sync(0xFFFFFFFFu, b, o);
        g += __shfl_down_sync(0xFFFFFFFFu, g, o);
    }
    if (lane == 0) {
        g_bhat[warp] = b;
        g_ghat[warp] = g;
    }
}

// 7) out[c,p] = gama_hat[p]*feat_src[c,p] + beta_hat[p]
__global__ void finalize_kernel(const float* __restrict__ fs, float* __restrict__ out) {
    int t = blockIdx.x * blockDim.x + threadIdx.x;
    if (t >= NF) return;
    int p = t % HW;
    out[t] = fmaf(g_ghat[p], fs[t], g_bhat[p]);
}

extern "C" void kernel_launch(void* const* d_in, const int* in_sizes, int n_in,
                              void* d_out, int out_size) {
    const float* fs = (const float*)d_in[0];   // feat_src (1,256,96,96)
    const float* fr = (const float*)d_in[1];   // feat_ref
    const float* ls = (const float*)d_in[2];   // landmarks_src (1,136,96,96)
    const float* lr = (const float*)d_in[3];   // landmarks_ref
    const int*   ms = (const int*)d_in[4];     // mask_src (1,1,96,96)
    const int*   mr = (const int*)d_in[5];     // mask_ref
    const float* w1 = (const float*)d_in[6];
    const float* b1 = (const float*)d_in[7];
    const float* w2 = (const float*)d_in[8];
    const float* b2 = (const float*)d_in[9];
    float* out = (float*)d_out;

    prep_concat<<<(NTOT + 255) / 256, 256>>>(fs, fr, ls, lr);
    prep_betagama<<<(HW + 255) / 256, 256>>>(fr, ms, mr, w1, b1, w2, b2);

    dim3 gemm_grid(HW / 128, HW / 128);        // 72 x 72
    sgemm_kernel<<<gemm_grid, 256>>>();

    dim3 cs_grid(HW / 256, NCHUNK);            // 36 x 32
    colstats_kernel<<<cs_grid, 256>>>();
    mergestats_kernel<<<HW / 256, 256>>>();
    rowsum_kernel<<<(HW * 32) / 256, 256>>>(); // one warp per row
    finalize_kernel<<<(NF + 255) / 256, 256>>>(fs, out);
}

// round 5
// speedup vs baseline: 1.0008x; 1.0008x over previous
#include <cuda_runtime.h>
#include <math_constants.h>

#define HW 9216            // 96*96
#define CK 392             // 256 + 136
#define NF (256 * HW)      // visual-feature element count
#define NTOT (CK * HW)     // concat element count = 3612672
#define NCHUNK 32
#define ROWS_PER_CHUNK (HW / NCHUNK)   // 288

// ---- static device scratch (no dynamic allocation allowed) ----
__device__ __align__(16) float g_SRC[NTOT];                 // (9216, 392) row-major
__device__ __align__(16) float g_REF[NTOT];                 // (392, 9216) row-major
__device__ __align__(16) float g_A[(size_t)HW * HW];        // 340 MB logits
__device__ float g_pm[NCHUNK * HW];
__device__ float g_ps[NCHUNK * HW];
__device__ float g_beta[HW], g_gama[HW], g_M[HW];
__device__ float g_colmax[HW], g_wb[HW], g_wg[HW];
__device__ float g_bhat[HW], g_ghat[HW];

// 1) Build the flattened concat buffers. The torch/jax "raw reshape" of the
//    channel-concat is exactly the contiguous flat buffer, so SRC/REF become
//    plain row-major GEMM operands.
__global__ void prep_concat(const float* __restrict__ fs, const float* __restrict__ fr,
                            const float* __restrict__ ls, const float* __restrict__ lr) {
    int t = blockIdx.x * blockDim.x + threadIdx.x;
    if (t >= NTOT) return;
    if (t < NF) {
        g_SRC[t] = 0.01f * fs[t];
        g_REF[t] = 0.01f * fr[t];
    } else {
        g_SRC[t] = ls[t - NF];
        g_REF[t] = lr[t - NF];
    }
}

// 2) 1x1 convs (256->1) + mask equality vector.
__global__ void prep_betagama(const float* __restrict__ fr,
                              const int* __restrict__ ms, const int* __restrict__ mr,
                              const float* __restrict__ w1, const float* __restrict__ b1,
                              const float* __restrict__ w2, const float* __restrict__ b2) {
    int p = blockIdx.x * blockDim.x + threadIdx.x;
    if (p >= HW) return;
    float b = b1[0], g = b2[0];
#pragma unroll 8
    for (int c = 0; c < 256; c++) {
        float v = fr[c * HW + p];          // coalesced across p
        b = fmaf(v, w1[c], b);
        g = fmaf(v, w2[c], g);
    }
    g_beta[p] = b;
    g_gama[p] = g;
    g_M[p] = (ms[p] == mr[p]) ? 1.0f : 0.0f;
}

// 3) fp32 SGEMM: g_A = g_SRC (9216x392) @ g_REF (392x9216).
//    128x128 block tile, BK=8, 256 threads, 8x8 per thread (split 4+4 to keep
//    LDS.128 conflict-free). K=392 = 49*8, M=N divisible by 128: no bounds checks.
__global__ void __launch_bounds__(256) sgemm_kernel() {
    __shared__ __align__(16) float As[8][128];
    __shared__ __align__(16) float Bs[8][128];
    const int tid = threadIdx.x;
    const int tx = tid & 15;        // 0..15  -> N direction
    const int ty = tid >> 4;        // 0..15  -> M direction
    const float* Ab = g_SRC + (size_t)blockIdx.y * 128 * CK;
    const float* Bb = g_REF + (size_t)blockIdx.x * 128;

    const int arow = tid >> 1, acol = (tid & 1) * 4;   // A: 128 rows x 8 k, float4/thread
    const int brow = tid >> 5, bcol = (tid & 31) * 4;  // B: 8 k x 128 cols, float4/thread

    float acc[8][8];
#pragma unroll
    for (int i = 0; i < 8; i++)
#pragma unroll
        for (int j = 0; j < 8; j++) acc[i][j] = 0.0f;

    for (int k0 = 0; k0 < CK; k0 += 8) {
        float4 av = *(const float4*)(Ab + (size_t)arow * CK + k0 + acol);
        float4 bv = *(const float4*)(Bb + (size_t)(k0 + brow) * HW + bcol);
        __syncthreads();
        As[acol + 0][arow] = av.x;
        As[acol + 1][arow] = av.y;
        As[acol + 2][arow] = av.z;
        As[acol + 3][arow] = av.w;
        *(float4*)&Bs[brow][bcol] = bv;
        __syncthreads();
#pragma unroll
        for (int k = 0; k < 8; k++) {
            float4 a0 = *(const float4*)&As[k][ty * 4];
            float4 a1 = *(const float4*)&As[k][ty * 4 + 64];
            float4 b0 = *(const float4*)&Bs[k][tx * 4];
            float4 b1 = *(const float4*)&Bs[k][tx * 4 + 64];
            float ar[8] = {a0.x, a0.y, a0.z, a0.w, a1.x, a1.y, a1.z, a1.w};
            float br[8] = {b0.x, b0.y, b0.z, b0.w, b1.x, b1.y, b1.z, b1.w};
#pragma unroll
            for (int i = 0; i < 8; i++)
#pragma unroll
                for (int j = 0; j < 8; j++) acc[i][j] = fmaf(ar[i], br[j], acc[i][j]);
        }
    }

    const size_t crow0 = (size_t)blockIdx.y * 128 + ty * 4;
    const size_t ccol0 = (size_t)blockIdx.x * 128 + tx * 4;
#pragma unroll
    for (int i = 0; i < 8; i++) {
        size_t r = crow0 + (i & 3) + (i >> 2) * 64;
        float* Cp = g_A + r * HW + ccol0;
        *(float4*)Cp        = make_float4(acc[i][0], acc[i][1], acc[i][2], acc[i][3]);
        *(float4*)(Cp + 64) = make_float4(acc[i][4], acc[i][5], acc[i][6], acc[i][7]);
    }
}

// 4) Per-column online (max, sum-exp) over a 288-row chunk. Thread = one column,
//    consecutive threads = consecutive columns -> fully coalesced A reads.
__global__ void colstats_kernel() {
    int j = blockIdx.x * blockDim.x + threadIdx.x;
    int i0 = blockIdx.y * ROWS_PER_CHUNK;
    float m = -CUDART_INF_F, s = 0.0f;
    const float* col = g_A + (size_t)i0 * HW + j;
    for (int i = 0; i < ROWS_PER_CHUNK; i++) {
        float v = col[(size_t)i * HW];
        float nm = fmaxf(m, v);
        s = s * __expf(m - nm) + __expf(v - nm);
        m = nm;
    }
    g_pm[blockIdx.y * HW + j] = m;
    g_ps[blockIdx.y * HW + j] = s;
}

// 5) Merge chunk partials; fold mask/beta/gama/colsum into per-column weights:
//    wb[j] = M[j]*beta[j]/colsum[j]  (softmax normalizer is over UNMASKED rows,
//    matching reference order softmax -> *M).
__global__ void mergestats_kernel() {
    int j = blockIdx.x * blockDim.x + threadIdx.x;
    float m = -CUDART_INF_F;
    for (int c = 0; c < NCHUNK; c++) m = fmaxf(m, g_pm[c * HW + j]);
    float s = 0.0f;
    for (int c = 0; c < NCHUNK; c++) s += g_ps[c * HW + j] * __expf(g_pm[c * HW + j] - m);
    g_colmax[j] = m;
    float inv = g_M[j] / s;
    g_wb[j] = g_beta[j] * inv;
    g_wg[j] = g_gama[j] * inv;
}

// 6) One warp per row: beta_hat[i] = sum_j exp(A[i,j]-colmax[j]) * wb[j], same for gama.
__global__ void rowsum_kernel() {
    int warp = (blockIdx.x * blockDim.x + threadIdx.x) >> 5;
    int lane = threadIdx.x & 31;
    const float* row = g_A + (size_t)warp * HW;
    float b = 0.0f, g = 0.0f;
    for (int j0 = lane * 4; j0 < HW; j0 += 128) {
        float4 v  = *(const float4*)(row + j0);
        float4 cm = *(const float4*)(g_colmax + j0);
        float4 wb = *(const float4*)(g_wb + j0);
        float4 wg = *(const float4*)(g_wg + j0);
        float e;
        e = __expf(v.x - cm.x); b = fmaf(e, wb.x, b); g = fmaf(e, wg.x, g);
        e = __expf(v.y - cm.y); b = fmaf(e, wb.y, b); g = fmaf(e, wg.y, g);
        e = __expf(v.z - cm.z); b = fmaf(e, wb.z, b); g = fmaf(e, wg.z, g);
        e = __expf(v.w - cm.w); b = fmaf(e, wb.w, b); g = fmaf(e, wg.w, g);
    }
#pragma unroll
    for (int o = 16; o > 0; o >>= 1) {
        b += __shfl_down_sync(0xFFFFFFFFu, b, o);
        g += __shfl_down_sync(0xFFFFFFFFu, g, o);
    }
    if (lane == 0) {
        g_bhat[warp] = b;
        g_ghat[warp] = g;
    }
}

// 7) out[c,p] = gama_hat[p]*feat_src[c,p] + beta_hat[p]
__global__ void finalize_kernel(const float* __restrict__ fs, float* __restrict__ out) {
    int t = blockIdx.x * blockDim.x + threadIdx.x;
    if (t >= NF) return;
    int p = t % HW;
    out[t] = fmaf(g_ghat[p], fs[t], g_bhat[p]);
}

extern "C" void kernel_launch(void* const* d_in, const int* in_sizes, int n_in,
                              void* d_out, int out_size) {
    const float* fs = (const float*)d_in[0];   // feat_src (1,256,96,96)
    const float* fr = (const float*)d_in[1];   // feat_ref
    const float* ls = (const float*)d_in[2];   // landmarks_src (1,136,96,96)
    const float* lr = (const float*)d_in[3];   // landmarks_ref
    const int*   ms = (const int*)d_in[4];     // mask_src (1,1,96,96)
    const int*   mr = (const int*)d_in[5];     // mask_ref
    const float* w1 = (const float*)d_in[6];
    const float* b1 = (const float*)d_in[7];
    const float* w2 = (const float*)d_in[8];
    const float* b2 = (const float*)d_in[9];
    float* out = (float*)d_out;

    prep_concat<<<(NTOT + 255) / 256, 256>>>(fs, fr, ls, lr);
    prep_betagama<<<(HW + 255) / 256, 256>>>(fr, ms, mr, w1, b1, w2, b2);

    dim3 gemm_grid(HW / 128, HW / 128);        // 72 x 72
    sgemm_kernel<<<gemm_grid, 256>>>();

    dim3 cs_grid(HW / 256, NCHUNK);            // 36 x 32
    colstats_kernel<<<cs_grid, 256>>>();
    mergestats_kernel<<<HW / 256, 256>>>();
    rowsum_kernel<<<(HW * 32) / 256, 256>>>(); // one warp per row
    finalize_kernel<<<(NF + 255) / 256, 256>>>(fs, out);
}